// round 1
// baseline (speedup 1.0000x reference)
#include <cuda_runtime.h>
#include <cstddef>

// ---------------------------------------------------------------------------
// Attention_11003706212887: out = softmax_causal((q Wq + bq)(k Wk + bk)^T / 32) (v Wv + bv)
// B=4, S=2048, D=1024, fp32.
// Round 1: pure-FP32 tiled pipeline (correctness + measurable baseline).
// ---------------------------------------------------------------------------

#define BM 128
#define BN 128
#define BK 16
#define PAD 4

static const int Bn = 4;
static const int Sq = 2048;
static const int Dd = 1024;

// Scratch (device globals: allocation-free per harness rules)
__device__ float g_WQ[(size_t)Bn * Sq * Dd];   // 33.5 MB
__device__ float g_WK[(size_t)Bn * Sq * Dd];
__device__ float g_WV[(size_t)Bn * Sq * Dd];
__device__ float g_S [(size_t)Bn * Sq * Sq];   // 67 MB

// ---------------------------------------------------------------------------
// C[M,N] = A[M,K] (row-major) @ B[K,N] (row-major) + bias[N]
// Requires M%128==0, N%128==0, K%16==0 (true for all our shapes).
// ---------------------------------------------------------------------------
__global__ __launch_bounds__(256) void gemm_nn_bias(
    const float* __restrict__ A, const float* __restrict__ B,
    const float* __restrict__ bias, float* __restrict__ C,
    int M, int N, int K)
{
    __shared__ float As[BK][BM + PAD];
    __shared__ float Bs[BK][BN + PAD];

    const int tid = threadIdx.x;
    const int tx = tid & 15, ty = tid >> 4;
    const int row0 = blockIdx.y * BM;
    const int col0 = blockIdx.x * BN;

    float acc[8][8] = {};

    for (int k0 = 0; k0 < K; k0 += BK) {
        // Load A tile transposed: A[m][k] -> As[k][m]
        #pragma unroll
        for (int i = 0; i < 2; i++) {
            int id = tid + i * 256;
            int m = id >> 2, kq = (id & 3) << 2;
            float4 a = *(const float4*)(A + (size_t)(row0 + m) * K + k0 + kq);
            As[kq + 0][m] = a.x; As[kq + 1][m] = a.y;
            As[kq + 2][m] = a.z; As[kq + 3][m] = a.w;
            // Load B tile: B[k][n] -> Bs[k][n]
            int kk = id >> 5, n = (id & 31) << 2;
            *(float4*)&Bs[kk][n] =
                *(const float4*)(B + (size_t)(k0 + kk) * N + col0 + n);
        }
        __syncthreads();

        #pragma unroll
        for (int k = 0; k < BK; k++) {
            float ra[8], rb[8];
            *(float4*)(ra)     = *(const float4*)&As[k][ty * 8];
            *(float4*)(ra + 4) = *(const float4*)&As[k][ty * 8 + 4];
            *(float4*)(rb)     = *(const float4*)&Bs[k][tx * 8];
            *(float4*)(rb + 4) = *(const float4*)&Bs[k][tx * 8 + 4];
            #pragma unroll
            for (int i = 0; i < 8; i++)
                #pragma unroll
                for (int j = 0; j < 8; j++)
                    acc[i][j] += ra[i] * rb[j];
        }
        __syncthreads();
    }

    #pragma unroll
    for (int i = 0; i < 8; i++) {
        const int r = row0 + ty * 8 + i;
        #pragma unroll
        for (int j = 0; j < 8; j += 4) {
            const int c = col0 + tx * 8 + j;
            float4 o;
            o.x = acc[i][j + 0] + bias[c + 0];
            o.y = acc[i][j + 1] + bias[c + 1];
            o.z = acc[i][j + 2] + bias[c + 2];
            o.w = acc[i][j + 3] + bias[c + 3];
            *(float4*)(C + (size_t)r * N + c) = o;
        }
    }
}

// ---------------------------------------------------------------------------
// Scores: S[b,i,j] = (WQ[b,i,:] . WK[b,j,:]) / 32  +  (j>i ? -1e9 : 0)
// Blocks strictly above the diagonal are skipped (softmax never reads them).
// ---------------------------------------------------------------------------
__global__ __launch_bounds__(256) void gemm_nt_causal(
    const float* __restrict__ WQ, const float* __restrict__ WK,
    float* __restrict__ Sc)
{
    const int bcol = blockIdx.x, brow = blockIdx.y, b = blockIdx.z;
    if (bcol > brow) return;

    __shared__ float As[BK][BM + PAD];
    __shared__ float Bs[BK][BN + PAD];

    const int tid = threadIdx.x;
    const int tx = tid & 15, ty = tid >> 4;
    const int row0 = brow * BM;
    const int col0 = bcol * BN;

    const float* A = WQ + (size_t)b * Sq * Dd;
    const float* Bm = WK + (size_t)b * Sq * Dd;
    float* C = Sc + (size_t)b * Sq * Sq;

    float acc[8][8] = {};

    for (int k0 = 0; k0 < Dd; k0 += BK) {
        #pragma unroll
        for (int i = 0; i < 2; i++) {
            int id = tid + i * 256;
            int m = id >> 2, kq = (id & 3) << 2;
            float4 a = *(const float4*)(A + (size_t)(row0 + m) * Dd + k0 + kq);
            As[kq + 0][m] = a.x; As[kq + 1][m] = a.y;
            As[kq + 2][m] = a.z; As[kq + 3][m] = a.w;
            float4 bb = *(const float4*)(Bm + (size_t)(col0 + m) * Dd + k0 + kq);
            Bs[kq + 0][m] = bb.x; Bs[kq + 1][m] = bb.y;
            Bs[kq + 2][m] = bb.z; Bs[kq + 3][m] = bb.w;
        }
        __syncthreads();

        #pragma unroll
        for (int k = 0; k < BK; k++) {
            float ra[8], rb[8];
            *(float4*)(ra)     = *(const float4*)&As[k][ty * 8];
            *(float4*)(ra + 4) = *(const float4*)&As[k][ty * 8 + 4];
            *(float4*)(rb)     = *(const float4*)&Bs[k][tx * 8];
            *(float4*)(rb + 4) = *(const float4*)&Bs[k][tx * 8 + 4];
            #pragma unroll
            for (int i = 0; i < 8; i++)
                #pragma unroll
                for (int j = 0; j < 8; j++)
                    acc[i][j] += ra[i] * rb[j];
        }
        __syncthreads();
    }

    const float scale = 0.03125f;  // 1/sqrt(1024)
    #pragma unroll
    for (int i = 0; i < 8; i++) {
        const int r = row0 + ty * 8 + i;
        #pragma unroll
        for (int j = 0; j < 8; j += 4) {
            const int c = col0 + tx * 8 + j;
            float4 o;
            o.x = acc[i][j + 0] * scale + ((c + 0) > r ? -1e9f : 0.0f);
            o.y = acc[i][j + 1] * scale + ((c + 1) > r ? -1e9f : 0.0f);
            o.z = acc[i][j + 2] * scale + ((c + 2) > r ? -1e9f : 0.0f);
            o.w = acc[i][j + 3] * scale + ((c + 3) > r ? -1e9f : 0.0f);
            *(float4*)(C + (size_t)r * Sq + c) = o;
        }
    }
}

// ---------------------------------------------------------------------------
// Causal row softmax in place: reads j<=i, writes normalized probs, zeros j>i.
// One 256-thread CTA per row; 8192 rows total.
// ---------------------------------------------------------------------------
__global__ __launch_bounds__(256) void softmax_causal(float* __restrict__ Sc)
{
    const int row = blockIdx.x;          // 0..8191
    const int b = row >> 11;
    const int i = row & 2047;
    float* p = Sc + ((size_t)b * Sq + i) * Sq;

    __shared__ float red[256];
    const int tid = threadIdx.x;

    float m = -1e30f;
    for (int j = tid; j <= i; j += 256) m = fmaxf(m, p[j]);
    red[tid] = m; __syncthreads();
    #pragma unroll
    for (int s = 128; s > 0; s >>= 1) {
        if (tid < s) red[tid] = fmaxf(red[tid], red[tid + s]);
        __syncthreads();
    }
    m = red[0];
    __syncthreads();

    float sum = 0.0f;
    for (int j = tid; j <= i; j += 256) {
        float e = expf(p[j] - m);
        p[j] = e;
        sum += e;
    }
    red[tid] = sum; __syncthreads();
    #pragma unroll
    for (int s = 128; s > 0; s >>= 1) {
        if (tid < s) red[tid] += red[tid + s];
        __syncthreads();
    }
    const float inv = 1.0f / red[0];

    for (int j = tid; j <= i; j += 256) p[j] *= inv;
    for (int j = i + 1 + tid; j < Sq; j += 256) p[j] = 0.0f;
}

// ---------------------------------------------------------------------------
// O[b] = P[b] (2048x2048) @ WV[b] (2048x1024), K-loop limited to (brow+1)*128
// (all P entries beyond a row's index are exact zeros, and blocks wholly
//  right of the diagonal are never needed).
// ---------------------------------------------------------------------------
__global__ __launch_bounds__(256) void gemm_nn_causalK(
    const float* __restrict__ P, const float* __restrict__ WV,
    float* __restrict__ O)
{
    const int b = blockIdx.z;
    const int brow = blockIdx.y;
    const int bcol = blockIdx.x;

    __shared__ float As[BK][BM + PAD];
    __shared__ float Bs[BK][BN + PAD];

    const int tid = threadIdx.x;
    const int tx = tid & 15, ty = tid >> 4;
    const int row0 = brow * BM;
    const int col0 = bcol * BN;

    const float* A = P + (size_t)b * Sq * Sq;       // M=2048, K=2048
    const float* Bm = WV + (size_t)b * Sq * Dd;     // K=2048, N=1024
    float* C = O + (size_t)b * Sq * Dd;

    const int Kend = (brow + 1) * BM;               // causal K-limit

    float acc[8][8] = {};

    for (int k0 = 0; k0 < Kend; k0 += BK) {
        #pragma unroll
        for (int i = 0; i < 2; i++) {
            int id = tid + i * 256;
            int m = id >> 2, kq = (id & 3) << 2;
            float4 a = *(const float4*)(A + (size_t)(row0 + m) * Sq + k0 + kq);
            As[kq + 0][m] = a.x; As[kq + 1][m] = a.y;
            As[kq + 2][m] = a.z; As[kq + 3][m] = a.w;
            int kk = id >> 5, n = (id & 31) << 2;
            *(float4*)&Bs[kk][n] =
                *(const float4*)(Bm + (size_t)(k0 + kk) * Dd + col0 + n);
        }
        __syncthreads();

        #pragma unroll
        for (int k = 0; k < BK; k++) {
            float ra[8], rb[8];
            *(float4*)(ra)     = *(const float4*)&As[k][ty * 8];
            *(float4*)(ra + 4) = *(const float4*)&As[k][ty * 8 + 4];
            *(float4*)(rb)     = *(const float4*)&Bs[k][tx * 8];
            *(float4*)(rb + 4) = *(const float4*)&Bs[k][tx * 8 + 4];
            #pragma unroll
            for (int i = 0; i < 8; i++)
                #pragma unroll
                for (int j = 0; j < 8; j++)
                    acc[i][j] += ra[i] * rb[j];
        }
        __syncthreads();
    }

    #pragma unroll
    for (int i = 0; i < 8; i++) {
        const int r = row0 + ty * 8 + i;
        #pragma unroll
        for (int j = 0; j < 8; j += 4) {
            const int c = col0 + tx * 8 + j;
            float4 o;
            o.x = acc[i][j + 0];
            o.y = acc[i][j + 1];
            o.z = acc[i][j + 2];
            o.w = acc[i][j + 3];
            *(float4*)(C + (size_t)r * Dd + c) = o;
        }
    }
}

// ---------------------------------------------------------------------------
// kernel_launch
// ---------------------------------------------------------------------------
extern "C" void kernel_launch(void* const* d_in, const int* in_sizes, int n_in,
                              void* d_out, int out_size)
{
    (void)in_sizes; (void)n_in; (void)out_size;

    const float* q    = (const float*)d_in[0];
    const float* k    = (const float*)d_in[1];
    const float* v    = (const float*)d_in[2];
    // d_in[3] = mask (causal, applied analytically)
    const float* Wq   = (const float*)d_in[4];
    const float* bq   = (const float*)d_in[5];
    const float* Wk   = (const float*)d_in[6];
    const float* bk   = (const float*)d_in[7];
    const float* Wv   = (const float*)d_in[8];
    const float* bv   = (const float*)d_in[9];
    float* out = (float*)d_out;

    float *gWQ, *gWK, *gWV, *gS;
    cudaGetSymbolAddress((void**)&gWQ, g_WQ);
    cudaGetSymbolAddress((void**)&gWK, g_WK);
    cudaGetSymbolAddress((void**)&gWV, g_WV);
    cudaGetSymbolAddress((void**)&gS,  g_S);

    const int M = Bn * Sq;   // 8192

    // Projections: [8192,1024] @ [1024,1024] + bias
    dim3 gProj(Dd / BN, M / BM);
    gemm_nn_bias<<<gProj, 256>>>(q, Wq, bq, gWQ, M, Dd, Dd);
    gemm_nn_bias<<<gProj, 256>>>(k, Wk, bk, gWK, M, Dd, Dd);
    gemm_nn_bias<<<gProj, 256>>>(v, Wv, bv, gWV, M, Dd, Dd);

    // Scores (causal, lower-triangular blocks only)
    dim3 gScores(Sq / BN, Sq / BM, Bn);
    gemm_nt_causal<<<gScores, 256>>>(gWQ, gWK, gS);

    // Row softmax
    softmax_causal<<<Bn * Sq, 256>>>(gS);

    // O = P @ WV (causal K-limit), writes d_out
    dim3 gPV(Dd / BN, Sq / BM, Bn);
    gemm_nn_causalK<<<gPV, 256>>>(gS, gWV, out);
}

// round 3
// speedup vs baseline: 3.8854x; 3.8854x over previous
#include <cuda_runtime.h>
#include <cuda_bf16.h>
#include <cstdint>
#include <cstddef>

// ---------------------------------------------------------------------------
// Attention_11003706212887 — Round 3: bf16x3 emulated-fp32 GEMMs on mma.sync
// (tcgen05 unusable: harness compiles via compute_103, not compute_103a).
// out = softmax_causal((q Wq + bq)(k Wk + bk)^T / 32) (v Wv + bv)
// B=4, S=2048, D=1024, fp32.
// ---------------------------------------------------------------------------

static const int Bn = 4;
static const int Sq = 2048;
static const int Dd = 1024;

typedef __nv_bfloat16 bf16;

// ---------------- device scratch (allocation-free) ----------------
#define AL __align__(256)
__device__ AL bf16 g_qh [(size_t)Bn * Sq * Dd];
__device__ AL bf16 g_ql [(size_t)Bn * Sq * Dd];
__device__ AL bf16 g_kh [(size_t)Bn * Sq * Dd];
__device__ AL bf16 g_kl [(size_t)Bn * Sq * Dd];
__device__ AL bf16 g_vh [(size_t)Bn * Sq * Dd];
__device__ AL bf16 g_vl [(size_t)Bn * Sq * Dd];
__device__ AL bf16 g_WTqh[(size_t)Dd * Dd];
__device__ AL bf16 g_WTql[(size_t)Dd * Dd];
__device__ AL bf16 g_WTkh[(size_t)Dd * Dd];
__device__ AL bf16 g_WTkl[(size_t)Dd * Dd];
__device__ AL bf16 g_WTvh[(size_t)Dd * Dd];
__device__ AL bf16 g_WTvl[(size_t)Dd * Dd];
__device__ AL bf16 g_WQh[(size_t)Bn * Sq * Dd];
__device__ AL bf16 g_WQl[(size_t)Bn * Sq * Dd];
__device__ AL bf16 g_WKh[(size_t)Bn * Sq * Dd];
__device__ AL bf16 g_WKl[(size_t)Bn * Sq * Dd];
__device__ AL bf16 g_WVth[(size_t)Bn * Dd * Sq];   // [b][d][s]
__device__ AL bf16 g_WVtl[(size_t)Bn * Dd * Sq];
__device__ AL float g_S [(size_t)Bn * Sq * Sq];    // fp32 scores
__device__ AL bf16 g_Ph[(size_t)Bn * Sq * Sq];
__device__ AL bf16 g_Pl[(size_t)Bn * Sq * Sq];

// ---------------- PTX helpers ----------------
__device__ __forceinline__ uint32_t smem_u32(const void* p) {
    uint32_t a;
    asm("{ .reg .u64 t; cvta.to.shared.u64 t, %1; cvt.u32.u64 %0, t; }" : "=r"(a) : "l"(p));
    return a;
}
// pack 2 floats -> bf16x2 (v0 in low half)
__device__ __forceinline__ uint32_t pk2(float v0, float v1) {
    uint32_t r;
    asm("cvt.rn.bf16x2.f32 %0, %1, %2;" : "=r"(r) : "f"(v1), "f"(v0));
    return r;
}
__device__ __forceinline__ float lo_f(uint32_t h) { return __uint_as_float(h << 16); }
__device__ __forceinline__ float hi_f(uint32_t h) { return __uint_as_float(h & 0xffff0000u); }

#define CP16(sa, ga) asm volatile("cp.async.cg.shared.global [%0], [%1], 16;" :: "r"(sa), "l"(ga) : "memory")
#define CP_COMMIT()  asm volatile("cp.async.commit_group;" ::: "memory")
#define CP_WAIT0()   asm volatile("cp.async.wait_group 0;" ::: "memory")

#define LDSM4(r, addr) \
    asm volatile("ldmatrix.sync.aligned.m8n8.x4.shared.b16 {%0,%1,%2,%3}, [%4];" \
        : "=r"((r)[0]), "=r"((r)[1]), "=r"((r)[2]), "=r"((r)[3]) : "r"(addr))
#define LDSM2(r, addr) \
    asm volatile("ldmatrix.sync.aligned.m8n8.x2.shared.b16 {%0,%1}, [%2];" \
        : "=r"((r)[0]), "=r"((r)[1]) : "r"(addr))

#define MMA16816(d, a, b) \
    asm volatile("mma.sync.aligned.m16n8k16.row.col.f32.bf16.bf16.f32 " \
        "{%0,%1,%2,%3}, {%4,%5,%6,%7}, {%8,%9}, {%0,%1,%2,%3};" \
        : "+f"((d)[0]), "+f"((d)[1]), "+f"((d)[2]), "+f"((d)[3]) \
        : "r"((a)[0]), "r"((a)[1]), "r"((a)[2]), "r"((a)[3]), "r"((b)[0]), "r"((b)[1]))

// ---------------- SMEM layout ----------------
// Each tile: 128 rows x 32 bf16, padded row stride 40 elems (80B) -> conflict-free
#define LDA_S 40
#define TILE_BYTES (128 * LDA_S * 2)   // 10240
#define OFF_AH 0
#define OFF_AL (TILE_BYTES)
#define OFF_BH (2 * TILE_BYTES)
#define OFF_BL (3 * TILE_BYTES)
#define BUF_BYTES (4 * TILE_BYTES)     // 40960
#define SMEM_TOTAL (2 * BUF_BYTES)     // 81920

// ---------------- GEMM core: C[128,128] += A[128,K] @ B[128,K]^T (bf16x3) ----
__device__ __forceinline__ void gemm_core(
    const bf16* __restrict__ Ah, const bf16* __restrict__ Al, int lda,
    const bf16* __restrict__ Bh, const bf16* __restrict__ Bl, int ldb,
    int kTotal, float acc[4][4][4])
{
    extern __shared__ char smem[];
    const uint32_t s32 = smem_u32(smem);
    const int tid = threadIdx.x, lane = tid & 31, wid = tid >> 5;
    const int wm = wid & 1, wn = wid >> 1;

    #pragma unroll
    for (int mt = 0; mt < 4; mt++)
        #pragma unroll
        for (int nt = 0; nt < 4; nt++)
            #pragma unroll
            for (int e = 0; e < 4; e++) acc[mt][nt][e] = 0.0f;

    // cp.async issue of one 32-wide K chunk into buffer p
    #define ISSUE(k0, p) do {                                                       \
        uint32_t sbase = s32 + (p) * BUF_BYTES;                                     \
        _Pragma("unroll")                                                           \
        for (int i = 0; i < 2; i++) {                                               \
            int idx = tid + i * 256;                                                \
            int row = idx >> 2, seg = idx & 3;                                      \
            uint32_t so = (uint32_t)(row * (LDA_S * 2) + seg * 16);                 \
            size_t gaoff = (size_t)row * lda + (k0) + seg * 8;                      \
            size_t gboff = (size_t)row * ldb + (k0) + seg * 8;                      \
            CP16(sbase + OFF_AH + so, Ah + gaoff);                                  \
            CP16(sbase + OFF_AL + so, Al + gaoff);                                  \
            CP16(sbase + OFF_BH + so, Bh + gboff);                                  \
            CP16(sbase + OFF_BL + so, Bl + gboff);                                  \
        }                                                                           \
        CP_COMMIT();                                                                \
    } while (0)

    ISSUE(0, 0);
    int p = 0;
    for (int k0 = 0; k0 < kTotal; k0 += 32) {
        CP_WAIT0();
        __syncthreads();
        if (k0 + 32 < kTotal) ISSUE(k0 + 32, p ^ 1);

        const uint32_t sb = s32 + p * BUF_BYTES;
        #pragma unroll
        for (int ks = 0; ks < 2; ks++) {
            uint32_t Af[4][4], Alf[4][4], Bf[4][2], Blf[4][2];
            const int arow = lane & 15;
            const int ak = ((lane >> 4) << 3) + ks * 16;
            #pragma unroll
            for (int mt = 0; mt < 4; mt++) {
                uint32_t off = (uint32_t)(((wm * 64 + mt * 16 + arow) * LDA_S + ak) * 2);
                LDSM4(Af[mt],  sb + OFF_AH + off);
                LDSM4(Alf[mt], sb + OFF_AL + off);
            }
            const int brow = lane & 7;
            const int bk = (((lane >> 3) & 1) << 3) + ks * 16;
            #pragma unroll
            for (int nt = 0; nt < 4; nt++) {
                uint32_t off = (uint32_t)(((wn * 32 + nt * 8 + brow) * LDA_S + bk) * 2);
                LDSM2(Bf[nt],  sb + OFF_BH + off);
                LDSM2(Blf[nt], sb + OFF_BL + off);
            }
            // 3 passes: hi*hi, hi*lo, lo*hi (lo*lo dropped: <=2^-18 rel)
            #pragma unroll
            for (int mt = 0; mt < 4; mt++)
                #pragma unroll
                for (int nt = 0; nt < 4; nt++) MMA16816(acc[mt][nt], Af[mt], Bf[nt]);
            #pragma unroll
            for (int mt = 0; mt < 4; mt++)
                #pragma unroll
                for (int nt = 0; nt < 4; nt++) MMA16816(acc[mt][nt], Af[mt], Blf[nt]);
            #pragma unroll
            for (int mt = 0; mt < 4; mt++)
                #pragma unroll
                for (int nt = 0; nt < 4; nt++) MMA16816(acc[mt][nt], Alf[mt], Bf[nt]);
        }
        p ^= 1;
    }
    #undef ISSUE
}

// epilogue coordinate helpers (per thread / fragment)
#define EPI_RC(mt, nt)                                                   \
    const int r = row0 + wm * 64 + (mt) * 16 + (lane >> 2);              \
    const int c = col0 + wn * 32 + (nt) * 8 + ((lane & 3) << 1);

__device__ __forceinline__ void st_split2(bf16* ph, bf16* pl, size_t off,
                                          float v0, float v1) {
    uint32_t h = pk2(v0, v1);
    uint32_t l = pk2(v0 - lo_f(h), v1 - hi_f(h));
    *(uint32_t*)(ph + off) = h;
    *(uint32_t*)(pl + off) = l;
}

// ---------------- GEMM kernels ----------------

// Q/K projection: C = X @ W^T + bias, output split to bf16 hi/lo [M x 1024]
__global__ void __launch_bounds__(256) proj_gemm(
    const bf16* __restrict__ Xh, const bf16* __restrict__ Xl,
    const bf16* __restrict__ WTh, const bf16* __restrict__ WTl,
    const float* __restrict__ bias,
    bf16* __restrict__ Oh, bf16* __restrict__ Ol)
{
    const int row0 = blockIdx.y * 128, col0 = blockIdx.x * 128;
    const int lane = threadIdx.x & 31, wid = threadIdx.x >> 5;
    const int wm = wid & 1, wn = wid >> 1;
    float acc[4][4][4];
    gemm_core(Xh + (size_t)row0 * Dd, Xl + (size_t)row0 * Dd, Dd,
              WTh + (size_t)col0 * Dd, WTl + (size_t)col0 * Dd, Dd, Dd, acc);
    #pragma unroll
    for (int mt = 0; mt < 4; mt++)
        #pragma unroll
        for (int nt = 0; nt < 4; nt++) {
            EPI_RC(mt, nt);
            float b0 = bias[c], b1 = bias[c + 1];
            st_split2(Oh, Ol, (size_t)r * Dd + c, acc[mt][nt][0] + b0, acc[mt][nt][1] + b1);
            st_split2(Oh, Ol, (size_t)(r + 8) * Dd + c, acc[mt][nt][2] + b0, acc[mt][nt][3] + b1);
        }
}

// V projection, transposed output: WVt[b][d][s] = sum_k WvT[d][k] v[b][s][k] + bv[d]
__global__ void __launch_bounds__(256) wvt_gemm(
    const bf16* __restrict__ WTh, const bf16* __restrict__ WTl,
    const bf16* __restrict__ Vh, const bf16* __restrict__ Vl,
    const float* __restrict__ bv,
    bf16* __restrict__ Oh, bf16* __restrict__ Ol)
{
    const int b = blockIdx.z;
    const int row0 = blockIdx.y * 128;   // d
    const int col0 = blockIdx.x * 128;   // s
    const int lane = threadIdx.x & 31, wid = threadIdx.x >> 5;
    const int wm = wid & 1, wn = wid >> 1;
    float acc[4][4][4];
    gemm_core(WTh + (size_t)row0 * Dd, WTl + (size_t)row0 * Dd, Dd,
              Vh + ((size_t)b * Sq + col0) * Dd, Vl + ((size_t)b * Sq + col0) * Dd, Dd,
              Dd, acc);
    bf16* oh = Oh + (size_t)b * Dd * Sq;
    bf16* ol = Ol + (size_t)b * Dd * Sq;
    #pragma unroll
    for (int mt = 0; mt < 4; mt++)
        #pragma unroll
        for (int nt = 0; nt < 4; nt++) {
            EPI_RC(mt, nt);
            float br0 = bv[r], br1 = bv[r + 8];
            st_split2(oh, ol, (size_t)r * Sq + c, acc[mt][nt][0] + br0, acc[mt][nt][1] + br0);
            st_split2(oh, ol, (size_t)(r + 8) * Sq + c, acc[mt][nt][2] + br1, acc[mt][nt][3] + br1);
        }
}

// Scores: S = WQ @ WK^T / 32 (lower-triangular blocks only), fp32 out
__global__ void __launch_bounds__(256) qk_gemm(
    const bf16* __restrict__ Qh, const bf16* __restrict__ Ql,
    const bf16* __restrict__ Kh, const bf16* __restrict__ Kl,
    float* __restrict__ Sc)
{
    const int bcol = blockIdx.x, brow = blockIdx.y, b = blockIdx.z;
    if (bcol > brow) return;
    const int row0 = brow * 128, col0 = bcol * 128;
    const int lane = threadIdx.x & 31, wid = threadIdx.x >> 5;
    const int wm = wid & 1, wn = wid >> 1;
    float acc[4][4][4];
    gemm_core(Qh + ((size_t)b * Sq + row0) * Dd, Ql + ((size_t)b * Sq + row0) * Dd, Dd,
              Kh + ((size_t)b * Sq + col0) * Dd, Kl + ((size_t)b * Sq + col0) * Dd, Dd,
              Dd, acc);
    float* C = Sc + (size_t)b * Sq * Sq;
    const float sc = 0.03125f;
    #pragma unroll
    for (int mt = 0; mt < 4; mt++)
        #pragma unroll
        for (int nt = 0; nt < 4; nt++) {
            EPI_RC(mt, nt);
            *(float2*)(C + (size_t)r * Sq + c) =
                make_float2(acc[mt][nt][0] * sc, acc[mt][nt][1] * sc);
            *(float2*)(C + (size_t)(r + 8) * Sq + c) =
                make_float2(acc[mt][nt][2] * sc, acc[mt][nt][3] * sc);
        }
}

// Output: O = P @ WVt^T with causal K-limit, fp32 out
__global__ void __launch_bounds__(256) pv_gemm(
    const bf16* __restrict__ Ph, const bf16* __restrict__ Pl,
    const bf16* __restrict__ Vh, const bf16* __restrict__ Vl,
    float* __restrict__ O)
{
    const int bcol = blockIdx.x, brow = blockIdx.y, b = blockIdx.z;
    const int row0 = brow * 128, col0 = bcol * 128;
    const int kEnd = (brow + 1) * 128;
    const int lane = threadIdx.x & 31, wid = threadIdx.x >> 5;
    const int wm = wid & 1, wn = wid >> 1;
    float acc[4][4][4];
    gemm_core(Ph + ((size_t)b * Sq + row0) * Sq, Pl + ((size_t)b * Sq + row0) * Sq, Sq,
              Vh + ((size_t)b * Dd + col0) * Sq, Vl + ((size_t)b * Dd + col0) * Sq, Sq,
              kEnd, acc);
    float* C = O + (size_t)b * Sq * Dd;
    #pragma unroll
    for (int mt = 0; mt < 4; mt++)
        #pragma unroll
        for (int nt = 0; nt < 4; nt++) {
            EPI_RC(mt, nt);
            *(float2*)(C + (size_t)r * Dd + c) =
                make_float2(acc[mt][nt][0], acc[mt][nt][1]);
            *(float2*)(C + (size_t)(r + 8) * Dd + c) =
                make_float2(acc[mt][nt][2], acc[mt][nt][3]);
        }
}

// ---------------- small prep kernels ----------------

// fp32 array -> bf16 hi/lo arrays (grid-stride over float4)
__global__ void __launch_bounds__(256) split_f32(
    const float4* __restrict__ in, uint2* __restrict__ oh, uint2* __restrict__ ol, int n4)
{
    for (int i = blockIdx.x * blockDim.x + threadIdx.x; i < n4; i += gridDim.x * blockDim.x) {
        float4 x = in[i];
        uint32_t h01 = pk2(x.x, x.y), h23 = pk2(x.z, x.w);
        uint32_t l01 = pk2(x.x - lo_f(h01), x.y - hi_f(h01));
        uint32_t l23 = pk2(x.z - lo_f(h23), x.w - hi_f(h23));
        oh[i] = make_uint2(h01, h23);
        ol[i] = make_uint2(l01, l23);
    }
}

// 1024x1024 fp32 transpose with split to bf16 hi/lo
__global__ void __launch_bounds__(256) transpose_split(
    const float* __restrict__ in, bf16* __restrict__ oh, bf16* __restrict__ ol)
{
    __shared__ float t[32][33];
    int x = blockIdx.x * 32 + threadIdx.x;
    int y = blockIdx.y * 32 + threadIdx.y;
    #pragma unroll
    for (int i = 0; i < 32; i += 8)
        t[threadIdx.y + i][threadIdx.x] = in[(size_t)(y + i) * Dd + x];
    __syncthreads();
    int x2 = blockIdx.y * 32 + threadIdx.x;
    int y2 = blockIdx.x * 32 + threadIdx.y;
    #pragma unroll
    for (int i = 0; i < 32; i += 8) {
        float v = t[threadIdx.x][threadIdx.y + i];
        bf16 h = __float2bfloat16_rn(v);
        bf16 l = __float2bfloat16_rn(v - __bfloat162float(h));
        oh[(size_t)(y2 + i) * Dd + x2] = h;
        ol[(size_t)(y2 + i) * Dd + x2] = l;
    }
}

// Causal row softmax: read fp32 S, write bf16 hi/lo probabilities (zero-padded
// up to the 128-block boundary that pv_gemm reads).
__global__ void __launch_bounds__(256) softmax_causal(
    const float* __restrict__ S, bf16* __restrict__ Ph, bf16* __restrict__ Pl)
{
    const int row = blockIdx.x;
    const int b = row >> 11;
    const int i = row & 2047;
    const float* s = S + ((size_t)b * Sq + i) * Sq;
    bf16* ph = Ph + ((size_t)b * Sq + i) * Sq;
    bf16* pl = Pl + ((size_t)b * Sq + i) * Sq;

    __shared__ float red[256];
    const int tid = threadIdx.x;

    float m = -1e30f;
    for (int j = tid; j <= i; j += 256) m = fmaxf(m, s[j]);
    red[tid] = m; __syncthreads();
    #pragma unroll
    for (int st = 128; st > 0; st >>= 1) {
        if (tid < st) red[tid] = fmaxf(red[tid], red[tid + st]);
        __syncthreads();
    }
    m = red[0];
    __syncthreads();

    float ev[8];
    float sum = 0.0f;
    int t = 0;
    for (int j = tid; j <= i; j += 256, t++) {
        float e = __expf(s[j] - m);
        ev[t] = e;
        sum += e;
    }
    red[tid] = sum; __syncthreads();
    #pragma unroll
    for (int st = 128; st > 0; st >>= 1) {
        if (tid < st) red[tid] += red[tid + st];
        __syncthreads();
    }
    const float inv = 1.0f / red[0];

    t = 0;
    for (int j = tid; j <= i; j += 256, t++) {
        float v = ev[t] * inv;
        bf16 h = __float2bfloat16_rn(v);
        bf16 l = __float2bfloat16_rn(v - __bfloat162float(h));
        ph[j] = h;
        pl[j] = l;
    }
    const int kEnd = ((i >> 7) + 1) << 7;
    const bf16 z = __float2bfloat16_rn(0.0f);
    for (int j = i + 1 + tid; j < kEnd; j += 256) { ph[j] = z; pl[j] = z; }
}

// ---------------- kernel_launch ----------------
extern "C" void kernel_launch(void* const* d_in, const int* in_sizes, int n_in,
                              void* d_out, int out_size)
{
    (void)in_sizes; (void)n_in; (void)out_size;

    const float* q  = (const float*)d_in[0];
    const float* k  = (const float*)d_in[1];
    const float* v  = (const float*)d_in[2];
    const float* Wq = (const float*)d_in[4];
    const float* bq = (const float*)d_in[5];
    const float* Wk = (const float*)d_in[6];
    const float* bk = (const float*)d_in[7];
    const float* Wv = (const float*)d_in[8];
    const float* bv = (const float*)d_in[9];
    float* out = (float*)d_out;

    bf16 *qh,*ql,*kh,*kl,*vh,*vl, *wtqh,*wtql,*wtkh,*wtkl,*wtvh,*wtvl;
    bf16 *wqh,*wql,*wkh,*wkl,*wvth,*wvtl, *pph,*ppl;
    float *sS;
    cudaGetSymbolAddress((void**)&qh, g_qh);   cudaGetSymbolAddress((void**)&ql, g_ql);
    cudaGetSymbolAddress((void**)&kh, g_kh);   cudaGetSymbolAddress((void**)&kl, g_kl);
    cudaGetSymbolAddress((void**)&vh, g_vh);   cudaGetSymbolAddress((void**)&vl, g_vl);
    cudaGetSymbolAddress((void**)&wtqh, g_WTqh); cudaGetSymbolAddress((void**)&wtql, g_WTql);
    cudaGetSymbolAddress((void**)&wtkh, g_WTkh); cudaGetSymbolAddress((void**)&wtkl, g_WTkl);
    cudaGetSymbolAddress((void**)&wtvh, g_WTvh); cudaGetSymbolAddress((void**)&wtvl, g_WTvl);
    cudaGetSymbolAddress((void**)&wqh, g_WQh); cudaGetSymbolAddress((void**)&wql, g_WQl);
    cudaGetSymbolAddress((void**)&wkh, g_WKh); cudaGetSymbolAddress((void**)&wkl, g_WKl);
    cudaGetSymbolAddress((void**)&wvth, g_WVth); cudaGetSymbolAddress((void**)&wvtl, g_WVtl);
    cudaGetSymbolAddress((void**)&sS, g_S);
    cudaGetSymbolAddress((void**)&pph, g_Ph);  cudaGetSymbolAddress((void**)&ppl, g_Pl);

    static bool attr_done = false;
    if (!attr_done) {
        cudaFuncSetAttribute(proj_gemm, cudaFuncAttributeMaxDynamicSharedMemorySize, SMEM_TOTAL);
        cudaFuncSetAttribute(wvt_gemm,  cudaFuncAttributeMaxDynamicSharedMemorySize, SMEM_TOTAL);
        cudaFuncSetAttribute(qk_gemm,   cudaFuncAttributeMaxDynamicSharedMemorySize, SMEM_TOTAL);
        cudaFuncSetAttribute(pv_gemm,   cudaFuncAttributeMaxDynamicSharedMemorySize, SMEM_TOTAL);
        attr_done = true;
    }

    const int M = Bn * Sq;                // 8192
    const int n4in = M * Dd / 4;          // 2,097,152

    // Split fp32 inputs into bf16 hi/lo
    split_f32<<<2048, 256>>>((const float4*)q, (uint2*)qh, (uint2*)ql, n4in);
    split_f32<<<2048, 256>>>((const float4*)k, (uint2*)kh, (uint2*)kl, n4in);
    split_f32<<<2048, 256>>>((const float4*)v, (uint2*)vh, (uint2*)vl, n4in);

    // Transpose + split weights
    const dim3 tGrid(32, 32), tBlk(32, 8);
    transpose_split<<<tGrid, tBlk>>>(Wq, wtqh, wtql);
    transpose_split<<<tGrid, tBlk>>>(Wk, wtkh, wtkl);
    transpose_split<<<tGrid, tBlk>>>(Wv, wtvh, wtvl);

    // Projections
    proj_gemm<<<dim3(Dd / 128, M / 128), 256, SMEM_TOTAL>>>(qh, ql, wtqh, wtql, bq, wqh, wql);
    proj_gemm<<<dim3(Dd / 128, M / 128), 256, SMEM_TOTAL>>>(kh, kl, wtkh, wtkl, bk, wkh, wkl);
    wvt_gemm<<<dim3(Sq / 128, Dd / 128, Bn), 256, SMEM_TOTAL>>>(wtvh, wtvl, vh, vl, bv, wvth, wvtl);

    // Scores (lower-triangular blocks), softmax, PV
    qk_gemm<<<dim3(Sq / 128, Sq / 128, Bn), 256, SMEM_TOTAL>>>(wqh, wql, wkh, wkl, sS);
    softmax_causal<<<Bn * Sq, 256>>>(sS, pph, ppl);
    pv_gemm<<<dim3(Dd / 128, Sq / 128, Bn), 256, SMEM_TOTAL>>>(pph, ppl, wvth, wvtl, out);
}